// round 6
// baseline (speedup 1.0000x reference)
#include <cuda_runtime.h>
#include <cuda_fp16.h>
#include <math.h>
#include <stdint.h>

// Problem dims
#define DI 1024
#define DH 2048
#define DO 50257
#define DB 1024

#define NBSTRIDE 208   // partials row stride (>= 197 n-blocks of logits)

// ---------------------------------------------------------------------------
// Device scratch
// ---------------------------------------------------------------------------
__device__ float  g_gates[(size_t)DB * 4 * DH];
__device__ __half g_wih_h[(size_t)4 * DH * DI];
__device__ __half g_whh_h[(size_t)4 * DH * DH];
__device__ __half g_in_h[(size_t)DB * DI];
__device__ __half g_hid_h[(size_t)DB * DH];
__device__ __half g_wlin_h[(size_t)DO * DH];
__device__ __half g_hn_h[(size_t)DB * DH];
__device__ float  g_partials[(size_t)DB * NBSTRIDE];
__device__ float  g_rowsum[DB];

// ---------------------------------------------------------------------------
// FMA-pipe exp. Valid for x in [-87, 80]; clamped.
// ---------------------------------------------------------------------------
__device__ __forceinline__ float fast_exp(float x) {
    x = fminf(fmaxf(x, -87.0f), 80.0f);
    float t = x * 1.4426950408889634f;   // log2(e)
    int   i = __float2int_rn(t);
    float f = t - (float)i;              // [-0.5, 0.5]
    float p = 1.3333557e-3f;
    p = fmaf(p, f, 9.6181291e-3f);
    p = fmaf(p, f, 5.5504109e-2f);
    p = fmaf(p, f, 2.4022651e-1f);
    p = fmaf(p, f, 6.9314718e-1f);
    p = fmaf(p, f, 1.0f);
    return p * __int_as_float((i + 127) << 23);
}

// ---------------------------------------------------------------------------
// fp16 mma.sync GEMM:  C[M,N] = sum_p A_p[M,Kp] @ B_p[N,Kp]^T (+bias)
// CTA tile 128x256, BK=32, 4-stage cp.async pipeline, 256 threads, 1 CTA/SM.
// Warp layout 2(m) x 4(n); warp tile 64x64 = 4x8 mma(16x8x16) frags.
// EXP_EPI: C = exp(acc + bias1), per-row partial sums -> partials[row][nblk].
// ---------------------------------------------------------------------------
struct GemmPass { const __half* A; const __half* B; int K; };
struct GemmArgs {
    GemmPass pass[2];
    int npass;
    const float* bias1;   // nullable
    const float* bias2;   // nullable
    float* C;
    float* partials;      // EXP_EPI only
    int N;
};

#define BM 128
#define BN 256
#define SH 40                           // smem row stride in halfs (80B)
#define A_STAGE_BYTES (BM * SH * 2)     // 10240
#define STAGE_BYTES   ((BM + BN) * SH * 2)  // 30720
#define NSTAGE 4
#define SMEM_BYTES (NSTAGE * STAGE_BYTES)   // 122880

__device__ __forceinline__ uint32_t smem_u32(const void* p) {
    return (uint32_t)__cvta_generic_to_shared(p);
}

__device__ __forceinline__ void cp_async16(uint32_t saddr, const void* gsrc, bool valid) {
    int ssz = valid ? 16 : 0;
    asm volatile("cp.async.cg.shared.global [%0], [%1], 16, %2;\n"
                 :: "r"(saddr), "l"(gsrc), "r"(ssz));
}

__device__ __forceinline__ void ldsm_x4(uint32_t* r, uint32_t saddr) {
    asm volatile("ldmatrix.sync.aligned.m8n8.x4.shared.b16 {%0,%1,%2,%3}, [%4];"
                 : "=r"(r[0]), "=r"(r[1]), "=r"(r[2]), "=r"(r[3]) : "r"(saddr));
}

__device__ __forceinline__ void mma_f16(float* c, const uint32_t* a,
                                        uint32_t b0, uint32_t b1) {
    asm volatile(
        "mma.sync.aligned.m16n8k16.row.col.f32.f16.f16.f32 "
        "{%0,%1,%2,%3}, {%4,%5,%6,%7}, {%8,%9}, {%0,%1,%2,%3};"
        : "+f"(c[0]), "+f"(c[1]), "+f"(c[2]), "+f"(c[3])
        : "r"(a[0]), "r"(a[1]), "r"(a[2]), "r"(a[3]), "r"(b0), "r"(b1));
}

__device__ __forceinline__ void load_chunk(const GemmArgs& g, int gchunk, int stage,
                                           int m0, int n0, uint32_t sbase, int tid) {
    int p = 0, c = gchunk;
    while (c >= (g.pass[p].K >> 5)) { c -= (g.pass[p].K >> 5); p++; }
    const __half* A = g.pass[p].A;
    const __half* B = g.pass[p].B;
    const int K = g.pass[p].K;
    const int k0 = c << 5;

    uint32_t sa = sbase + stage * STAGE_BYTES;
    uint32_t sb = sa + A_STAGE_BYTES;

    // A tile: 128 rows x 32 halfs (4 x 16B per row) -> 512 ops, 2/thread
#pragma unroll
    for (int i = 0; i < 2; i++) {
        int idx = tid + i * 256;
        int row = idx >> 2, c8 = idx & 3;
        const __half* src = A + (size_t)(m0 + row) * K + k0 + c8 * 8;
        cp_async16(sa + (row * SH + c8 * 8) * 2, src, true);
    }
    // B tile: 256 rows x 32 halfs -> 1024 ops, 4/thread (ragged zfill)
#pragma unroll
    for (int i = 0; i < 4; i++) {
        int idx = tid + i * 256;
        int row = idx >> 2, c8 = idx & 3;
        int nrow = n0 + row;
        bool ok = nrow < g.N;
        const __half* src = B + (size_t)(ok ? nrow : 0) * K + k0 + c8 * 8;
        cp_async16(sb + (row * SH + c8 * 8) * 2, src, ok);
    }
}

template <bool EXP_EPI>
__global__ __launch_bounds__(256, 1) void f16_gemm_kernel(GemmArgs g) {
    extern __shared__ __half smem[];
    const int tid = threadIdx.x;
    const int lane = tid & 31;
    const int wid = tid >> 5;
    const int warp_m = wid >> 2;  // 0..1 -> 64-row slice
    const int warp_n = wid & 3;   // 0..3 -> 64-col slice
    const int gq = lane >> 2;     // 0..7
    const int tq = lane & 3;      // 0..3

    const int m0 = blockIdx.x * BM;   // x = m fast: CTAs sharing B tile adjacent
    const int n0 = blockIdx.y * BN;
    const uint32_t sbase = smem_u32(smem);

    // ldmatrix per-lane base offsets (halfs, relative to tile base)
    const int arow = warp_m * 64 + (lane & 15);
    const int acol = ((lane >> 4) & 1) * 8;
    const int brow = warp_n * 64 + (lane & 7) + ((lane >> 4) & 1) * 8;
    const int bcol = ((lane >> 3) & 1) * 8;

    float acc[4][8][4];
#pragma unroll
    for (int i = 0; i < 4; i++)
#pragma unroll
        for (int j = 0; j < 8; j++)
#pragma unroll
            for (int k = 0; k < 4; k++) acc[i][j][k] = 0.f;

    int total = 0;
    for (int p = 0; p < g.npass; p++) total += g.pass[p].K >> 5;

    // prologue: NSTAGE-1 chunks in flight
#pragma unroll
    for (int j = 0; j < NSTAGE - 1; j++) {
        if (j < total) load_chunk(g, j, j, m0, n0, sbase, tid);
        asm volatile("cp.async.commit_group;");
    }

    for (int j = 0; j < total; j++) {
        const int stage = j & (NSTAGE - 1);
        asm volatile("cp.async.wait_group %0;" :: "n"(NSTAGE - 2));
        __syncthreads();

        // issue next load before compute (into the buffer freed last iter)
        if (j + NSTAGE - 1 < total)
            load_chunk(g, j + NSTAGE - 1, (j + NSTAGE - 1) & (NSTAGE - 1), m0, n0, sbase, tid);
        asm volatile("cp.async.commit_group;");

        const uint32_t sa = sbase + stage * STAGE_BYTES;
        const uint32_t sb = sa + A_STAGE_BYTES;

#pragma unroll
        for (int ks = 0; ks < 2; ks++) {
            const int kk = ks * 16;
            uint32_t a[4][4];
#pragma unroll
            for (int mi = 0; mi < 4; mi++)
                ldsm_x4(a[mi], sa + ((arow + mi * 16) * SH + acol + kk) * 2);
            uint32_t b[4][4];
#pragma unroll
            for (int nip = 0; nip < 4; nip++)
                ldsm_x4(b[nip], sb + ((brow + nip * 16) * SH + bcol + kk) * 2);
#pragma unroll
            for (int mi = 0; mi < 4; mi++)
#pragma unroll
                for (int nip = 0; nip < 4; nip++) {
                    mma_f16(acc[mi][2 * nip],     a[mi], b[nip][0], b[nip][1]);
                    mma_f16(acc[mi][2 * nip + 1], a[mi], b[nip][2], b[nip][3]);
                }
        }
    }
    __syncthreads();   // mainloop done; smem reusable below

    const bool hb1 = (g.bias1 != nullptr);
    const bool hb2 = (g.bias2 != nullptr);

    if (!EXP_EPI) {
        // plain epilogue — scalar stores (N may be odd)
#pragma unroll
        for (int mi = 0; mi < 4; mi++) {
            const int r0 = m0 + warp_m * 64 + mi * 16 + gq;
#pragma unroll
            for (int ni = 0; ni < 8; ni++) {
                const int col = n0 + warp_n * 64 + ni * 8 + 2 * tq;
                float* p0 = g.C + (size_t)r0 * g.N;
                float* p1 = g.C + (size_t)(r0 + 8) * g.N;
                if (col < g.N) {
                    float b0 = 0.f;
                    if (hb1) b0 += __ldg(g.bias1 + col);
                    if (hb2) b0 += __ldg(g.bias2 + col);
                    p0[col] = acc[mi][ni][0] + b0;
                    p1[col] = acc[mi][ni][2] + b0;
                }
                if (col + 1 < g.N) {
                    float b1 = 0.f;
                    if (hb1) b1 += __ldg(g.bias1 + col + 1);
                    if (hb2) b1 += __ldg(g.bias2 + col + 1);
                    p0[col + 1] = acc[mi][ni][1] + b1;
                    p1[col + 1] = acc[mi][ni][3] + b1;
                }
            }
        }
    } else {
        // exp epilogue: C = exp(acc + bias1); per-row partial sums
        float* red = (float*)smem;   // [4][128]
#pragma unroll
        for (int mi = 0; mi < 4; mi++) {
            const int rl0 = warp_m * 64 + mi * 16 + gq;   // local row
            const int r0 = m0 + rl0;
            float rs0 = 0.f, rs1 = 0.f;
            float* p0 = g.C + (size_t)r0 * g.N;
            float* p1 = g.C + (size_t)(r0 + 8) * g.N;
#pragma unroll
            for (int ni = 0; ni < 8; ni++) {
                const int col = n0 + warp_n * 64 + ni * 8 + 2 * tq;
                if (col < g.N) {
                    float b0 = __ldg(g.bias1 + col);
                    float e0 = fast_exp(acc[mi][ni][0] + b0);
                    float e2 = fast_exp(acc[mi][ni][2] + b0);
                    p0[col] = e0; p1[col] = e2;
                    rs0 += e0; rs1 += e2;
                }
                if (col + 1 < g.N) {
                    float b1 = __ldg(g.bias1 + col + 1);
                    float e1 = fast_exp(acc[mi][ni][1] + b1);
                    float e3 = fast_exp(acc[mi][ni][3] + b1);
                    p0[col + 1] = e1; p1[col + 1] = e3;
                    rs0 += e1; rs1 += e3;
                }
            }
            // reduce across tq lanes (same row within 4-lane group)
            rs0 += __shfl_xor_sync(0xffffffffu, rs0, 1);
            rs0 += __shfl_xor_sync(0xffffffffu, rs0, 2);
            rs1 += __shfl_xor_sync(0xffffffffu, rs1, 1);
            rs1 += __shfl_xor_sync(0xffffffffu, rs1, 2);
            if (tq == 0) {
                red[warp_n * 128 + rl0]     = rs0;
                red[warp_n * 128 + rl0 + 8] = rs1;
            }
        }
        __syncthreads();
        if (tid < 128) {
            float s = red[tid] + red[128 + tid] + red[256 + tid] + red[384 + tid];
            g.partials[(size_t)(m0 + tid) * NBSTRIDE + blockIdx.y] = s;
        }
    }
}

// ---------------------------------------------------------------------------
// partials -> rowsum
// ---------------------------------------------------------------------------
__global__ void reduce_rowsum_kernel(const float* __restrict__ partials,
                                     float* __restrict__ rowsum, int nblocks) {
    int r = blockIdx.x * blockDim.x + threadIdx.x;
    if (r >= DB) return;
    const float* p = partials + (size_t)r * NBSTRIDE;
    float s = 0.f;
    for (int i = 0; i < nblocks; i++) s += p[i];
    rowsum[r] = s;
}

// scale: probs (holding exp values) *= 1/rowsum
__global__ __launch_bounds__(256) void softmax_scale_kernel(float* __restrict__ x,
                                                            const float* __restrict__ rowsum,
                                                            int N) {
    float* p = x + (size_t)blockIdx.x * N;
    const float inv = 1.f / rowsum[blockIdx.x];
    for (int i = threadIdx.x; i < N; i += 256) p[i] *= inv;
}

// ---------------------------------------------------------------------------
// fp32 -> fp16 conversion (n divisible by 8)
// ---------------------------------------------------------------------------
__global__ __launch_bounds__(256) void f2h_kernel(const float* __restrict__ x,
                                                  __half* __restrict__ y, int n) {
    int i = (blockIdx.x * blockDim.x + threadIdx.x) * 8;
    if (i >= n) return;
    float4 v0 = *reinterpret_cast<const float4*>(x + i);
    float4 v1 = *reinterpret_cast<const float4*>(x + i + 4);
    __half2 h[4];
    h[0] = __floats2half2_rn(v0.x, v0.y);
    h[1] = __floats2half2_rn(v0.z, v0.w);
    h[2] = __floats2half2_rn(v1.x, v1.y);
    h[3] = __floats2half2_rn(v1.z, v1.w);
    *reinterpret_cast<uint4*>(y + i) = *reinterpret_cast<uint4*>(h);
}

// ---------------------------------------------------------------------------
// LSTM cell elementwise; also emits hn in fp16 for the logits GEMM
// ---------------------------------------------------------------------------
__device__ __forceinline__ float sigmoidf_(float x) { return 1.f / (1.f + expf(-x)); }

__global__ void lstm_cell_kernel(const float* __restrict__ gates,
                                 const float* __restrict__ c0,
                                 float* __restrict__ hn,
                                 float* __restrict__ cn,
                                 __half* __restrict__ hn_h) {
    int idx = blockIdx.x * blockDim.x + threadIdx.x;
    if (idx >= DB * DH) return;
    int b = idx / DH;
    int h = idx % DH;
    const float* gr = gates + (size_t)b * 4 * DH;
    float ig = sigmoidf_(gr[h]);
    float fg = sigmoidf_(gr[DH + h]);
    float gg = tanhf(gr[2 * DH + h]);
    float og = sigmoidf_(gr[3 * DH + h]);
    float c = fg * c0[idx] + ig * gg;
    float hv = og * tanhf(c);
    cn[idx] = c;
    hn[idx] = hv;
    hn_h[idx] = __float2half_rn(hv);
}

// ---------------------------------------------------------------------------
extern "C" void kernel_launch(void* const* d_in, const int* in_sizes, int n_in,
                              void* d_out, int out_size)
{
    const float* input  = (const float*)d_in[0];
    const float* hidden = (const float*)d_in[1];
    const float* c0     = (const float*)d_in[2];
    const float* w_ih   = (const float*)d_in[3];
    const float* w_hh   = (const float*)d_in[4];
    const float* b_ih   = (const float*)d_in[5];
    const float* b_hh   = (const float*)d_in[6];
    const float* w_lin  = (const float*)d_in[7];
    const float* b_lin  = (const float*)d_in[8];

    float* out   = (float*)d_out;
    float* probs = out;                              // [B, O]
    float* hn    = out + (size_t)DB * DO;            // [B, H]
    float* cn    = hn + (size_t)DB * DH;             // [B, H]

    float *gates, *rowsum, *partials;
    __half *wih_h, *whh_h, *in_h, *hid_h, *wlin_h, *hn_h;
    cudaGetSymbolAddress((void**)&gates,    g_gates);
    cudaGetSymbolAddress((void**)&rowsum,   g_rowsum);
    cudaGetSymbolAddress((void**)&partials, g_partials);
    cudaGetSymbolAddress((void**)&wih_h,    g_wih_h);
    cudaGetSymbolAddress((void**)&whh_h,    g_whh_h);
    cudaGetSymbolAddress((void**)&in_h,     g_in_h);
    cudaGetSymbolAddress((void**)&hid_h,    g_hid_h);
    cudaGetSymbolAddress((void**)&wlin_h,   g_wlin_h);
    cudaGetSymbolAddress((void**)&hn_h,     g_hn_h);

    cudaFuncSetAttribute(f16_gemm_kernel<false>,
                         cudaFuncAttributeMaxDynamicSharedMemorySize, SMEM_BYTES);
    cudaFuncSetAttribute(f16_gemm_kernel<true>,
                         cudaFuncAttributeMaxDynamicSharedMemorySize, SMEM_BYTES);

    // fp16 conversions
    {
        int n;
        n = DB * DI;      f2h_kernel<<<(n / 8 + 255) / 256, 256>>>(input,  in_h,  n);
        n = DB * DH;      f2h_kernel<<<(n / 8 + 255) / 256, 256>>>(hidden, hid_h, n);
        n = 4 * DH * DI;  f2h_kernel<<<(n / 8 + 255) / 256, 256>>>(w_ih,   wih_h, n);
        n = 4 * DH * DH;  f2h_kernel<<<(n / 8 + 255) / 256, 256>>>(w_hh,   whh_h, n);
        n = DO * DH;      f2h_kernel<<<(n / 8 + 255) / 256, 256>>>(w_lin,  wlin_h, n);
    }

    // gates = input @ w_ih^T + h0 @ w_hh^T + b_ih + b_hh
    {
        GemmArgs a;
        a.pass[0] = { in_h,  wih_h, DI };
        a.pass[1] = { hid_h, whh_h, DH };
        a.npass = 2;
        a.bias1 = b_ih;
        a.bias2 = b_hh;
        a.C = gates;
        a.partials = nullptr;
        a.N = 4 * DH;
        dim3 grid(DB / BM, (4 * DH) / BN);
        f16_gemm_kernel<false><<<grid, 256, SMEM_BYTES>>>(a);
    }

    // LSTM cell -> hn, cn (+ hn fp16)
    lstm_cell_kernel<<<(DB * DH + 255) / 256, 256>>>(gates, c0, hn, cn, hn_h);

    // probs_unnorm = exp(hn @ w_lin^T + b_lin); partial row sums
    const int nblocks = (DO + BN - 1) / BN;   // 197
    {
        GemmArgs a;
        a.pass[0] = { hn_h, wlin_h, DH };
        a.npass = 1;
        a.bias1 = b_lin;
        a.bias2 = nullptr;
        a.C = probs;
        a.partials = partials;
        a.N = DO;
        dim3 grid(DB / BM, nblocks);
        f16_gemm_kernel<true><<<grid, 256, SMEM_BYTES>>>(a);
    }

    // rowsum + scale
    reduce_rowsum_kernel<<<4, 256>>>(partials, rowsum, nblocks);
    softmax_scale_kernel<<<DB, 256>>>(probs, rowsum, DO);
}

// round 7
// speedup vs baseline: 1.2221x; 1.2221x over previous
#include <cuda_runtime.h>
#include <cuda_fp16.h>
#include <math.h>
#include <stdint.h>

// Problem dims
#define DI 1024
#define DH 2048
#define DO 50257
#define DB 1024

#define NBSTRIDE 400   // partials row stride (>= 393 n-blocks at BN=128)

// ---------------------------------------------------------------------------
// Device scratch
// ---------------------------------------------------------------------------
__device__ float  g_gates[(size_t)DB * 4 * DH];
__device__ __half g_wih_h[(size_t)4 * DH * DI];
__device__ __half g_whh_h[(size_t)4 * DH * DH];
__device__ __half g_in_h[(size_t)DB * DI];
__device__ __half g_hid_h[(size_t)DB * DH];
__device__ __half g_wlin_h[(size_t)DO * DH];
__device__ __half g_hn_h[(size_t)DB * DH];
__device__ float  g_partials[(size_t)DB * NBSTRIDE];
__device__ float  g_rowsum[DB];

// ---------------------------------------------------------------------------
// FMA-pipe exp. Valid for x in [-87, 80]; clamped.
// ---------------------------------------------------------------------------
__device__ __forceinline__ float fast_exp(float x) {
    x = fminf(fmaxf(x, -87.0f), 80.0f);
    float t = x * 1.4426950408889634f;   // log2(e)
    int   i = __float2int_rn(t);
    float f = t - (float)i;              // [-0.5, 0.5]
    float p = 1.3333557e-3f;
    p = fmaf(p, f, 9.6181291e-3f);
    p = fmaf(p, f, 5.5504109e-2f);
    p = fmaf(p, f, 2.4022651e-1f);
    p = fmaf(p, f, 6.9314718e-1f);
    p = fmaf(p, f, 1.0f);
    return p * __int_as_float((i + 127) << 23);
}

// ---------------------------------------------------------------------------
// fp16 mma.sync GEMM:  C[M,N] = sum_p A_p[M,Kp] @ B_p[N,Kp]^T (+bias)
// CTA tile 128x128, BK=64 halfs, 2-stage cp.async pipeline, 256 threads.
// Warp layout 4(m) x 2(n); warp tile 32x64 = 2x8 mma(16x8x16) frags.
// EXP_EPI: C = exp(acc + bias1); per-row partial sums -> partials[row][nblk].
// ---------------------------------------------------------------------------
struct GemmPass { const __half* A; const __half* B; int K; };
struct GemmArgs {
    GemmPass pass[2];
    int npass;
    const float* bias1;  // nullable
    const float* bias2;  // nullable
    float* C;
    float* partials;     // EXP_EPI only
    int N;
};

#define BK 64
#define SH 72                         // smem row stride in halfs (144B, 16B-aligned)
#define STAGE_HALFS (256 * SH)        // A rows 0-127, B rows 128-255
#define STAGE_BYTES (STAGE_HALFS * 2)
#define SMEM_BYTES  (2 * STAGE_BYTES) // 73728 B

__device__ __forceinline__ uint32_t smem_u32(const void* p) {
    return (uint32_t)__cvta_generic_to_shared(p);
}

__device__ __forceinline__ void cp_async16(uint32_t saddr, const void* gsrc, bool valid) {
    int ssz = valid ? 16 : 0;
    asm volatile("cp.async.cg.shared.global [%0], [%1], 16, %2;\n"
                 :: "r"(saddr), "l"(gsrc), "r"(ssz));
}

__device__ __forceinline__ void ldsm_x4(uint32_t* r, uint32_t saddr) {
    asm volatile("ldmatrix.sync.aligned.m8n8.x4.shared.b16 {%0,%1,%2,%3}, [%4];"
                 : "=r"(r[0]), "=r"(r[1]), "=r"(r[2]), "=r"(r[3]) : "r"(saddr));
}

__device__ __forceinline__ void mma_f16(float* c, const uint32_t* a,
                                        uint32_t b0, uint32_t b1) {
    asm volatile(
        "mma.sync.aligned.m16n8k16.row.col.f32.f16.f16.f32 "
        "{%0,%1,%2,%3}, {%4,%5,%6,%7}, {%8,%9}, {%0,%1,%2,%3};"
        : "+f"(c[0]), "+f"(c[1]), "+f"(c[2]), "+f"(c[3])
        : "r"(a[0]), "r"(a[1]), "r"(a[2]), "r"(a[3]), "r"(b0), "r"(b1));
}

__device__ __forceinline__ void load_chunk(const GemmArgs& g, int gchunk, int stage,
                                           int m0, int n0, uint32_t sbase, int tid) {
    int p = 0, c = gchunk;
    while (c >= (g.pass[p].K >> 6)) { c -= (g.pass[p].K >> 6); p++; }
    const __half* A = g.pass[p].A;
    const __half* B = g.pass[p].B;
    const int K = g.pass[p].K;
    const int k0 = c << 6;

    uint32_t sa = sbase + stage * STAGE_BYTES;
    uint32_t sb = sa + 128 * SH * 2;

#pragma unroll
    for (int i = 0; i < 4; i++) {
        int idx = tid + i * 256;
        int row = idx >> 3, c8 = idx & 7;
        const __half* src = A + (size_t)(m0 + row) * K + k0 + c8 * 8;
        cp_async16(sa + (row * SH + c8 * 8) * 2, src, true);
    }
#pragma unroll
    for (int i = 0; i < 4; i++) {
        int idx = tid + i * 256;
        int row = idx >> 3, c8 = idx & 7;
        int nrow = n0 + row;
        bool ok = nrow < g.N;
        const __half* src = B + (size_t)(ok ? nrow : 0) * K + k0 + c8 * 8;
        cp_async16(sb + (row * SH + c8 * 8) * 2, src, ok);
    }
}

template <bool EXP_EPI>
__global__ __launch_bounds__(256, 2) void f16_gemm_kernel(GemmArgs g) {
    extern __shared__ __half smem[];
    const int tid = threadIdx.x;
    const int lane = tid & 31;
    const int wid = tid >> 5;
    const int warp_m = wid & 3;   // 0..3  -> 32-row slice
    const int warp_n = wid >> 2;  // 0..1  -> 64-col slice
    const int gq = lane >> 2;     // 0..7
    const int tq = lane & 3;      // 0..3

    const int m0 = blockIdx.x * 128;   // x = m fast: CTAs sharing B tile adjacent
    const int n0 = blockIdx.y * 128;
    const uint32_t sbase = smem_u32(smem);

    const int aoff = (warp_m * 32 + (lane & 7) + ((lane >> 3) & 1) * 8) * SH
                   + ((lane >> 4) & 1) * 8;
    const int boff = (warp_n * 64 + (lane & 7) + ((lane >> 4) & 1) * 8) * SH
                   + ((lane >> 3) & 1) * 8;

    float acc[2][8][4];
#pragma unroll
    for (int i = 0; i < 2; i++)
#pragma unroll
        for (int j = 0; j < 8; j++)
#pragma unroll
            for (int k = 0; k < 4; k++) acc[i][j][k] = 0.f;

    int total = 0;
    for (int p = 0; p < g.npass; p++) total += g.pass[p].K >> 6;

    load_chunk(g, 0, 0, m0, n0, sbase, tid);
    asm volatile("cp.async.commit_group;");
    if (total > 1) {
        load_chunk(g, 1, 1, m0, n0, sbase, tid);
        asm volatile("cp.async.commit_group;");
    }

    for (int j = 0; j < total; j++) {
        const int stage = j & 1;
        if (j == total - 1)
            asm volatile("cp.async.wait_group 0;");
        else
            asm volatile("cp.async.wait_group 1;");
        __syncthreads();

        const uint32_t sa = sbase + stage * STAGE_BYTES;
        const uint32_t sb = sa + 128 * SH * 2;

#pragma unroll
        for (int ks = 0; ks < BK / 16; ks++) {
            const int kk = ks * 16;
            uint32_t a[2][4];
            ldsm_x4(a[0], sa + (aoff + kk) * 2);
            ldsm_x4(a[1], sa + (aoff + 16 * SH + kk) * 2);
            uint32_t b[4][4];
#pragma unroll
            for (int nip = 0; nip < 4; nip++)
                ldsm_x4(b[nip], sb + (boff + nip * 16 * SH + kk) * 2);
#pragma unroll
            for (int mi = 0; mi < 2; mi++)
#pragma unroll
                for (int nip = 0; nip < 4; nip++) {
                    mma_f16(acc[mi][2 * nip],     a[mi], b[nip][0], b[nip][1]);
                    mma_f16(acc[mi][2 * nip + 1], a[mi], b[nip][2], b[nip][3]);
                }
        }
        __syncthreads();

        if (j + 2 < total) {
            load_chunk(g, j + 2, stage, m0, n0, sbase, tid);
            asm volatile("cp.async.commit_group;");
        }
    }

    const bool hb1 = (g.bias1 != nullptr);
    const bool hb2 = (g.bias2 != nullptr);

    if (!EXP_EPI) {
        // plain epilogue — scalar stores (N may be odd)
#pragma unroll
        for (int mi = 0; mi < 2; mi++) {
            const int r0 = m0 + warp_m * 32 + mi * 16 + gq;
#pragma unroll
            for (int ni = 0; ni < 8; ni++) {
                const int col = n0 + warp_n * 64 + ni * 8 + 2 * tq;
                float* p0 = g.C + (size_t)r0 * g.N;
                float* p1 = g.C + (size_t)(r0 + 8) * g.N;
                if (col < g.N) {
                    float b0 = 0.f;
                    if (hb1) b0 += __ldg(g.bias1 + col);
                    if (hb2) b0 += __ldg(g.bias2 + col);
                    p0[col] = acc[mi][ni][0] + b0;
                    p1[col] = acc[mi][ni][2] + b0;
                }
                if (col + 1 < g.N) {
                    float b1 = 0.f;
                    if (hb1) b1 += __ldg(g.bias1 + col + 1);
                    if (hb2) b1 += __ldg(g.bias2 + col + 1);
                    p0[col + 1] = acc[mi][ni][1] + b1;
                    p1[col + 1] = acc[mi][ni][3] + b1;
                }
            }
        }
    } else {
        // exp epilogue: C = exp(acc + bias1); per-row partial sums
        __syncthreads();               // all warps done with smem tiles
        float* red = (float*)smem;     // [2 warp_n][128 rows]
#pragma unroll
        for (int mi = 0; mi < 2; mi++) {
            const int rl0 = warp_m * 32 + mi * 16 + gq;   // local row (and +8)
            const int r0 = m0 + rl0;
            float rs0 = 0.f, rs1 = 0.f;
            float* p0 = g.C + (size_t)r0 * g.N;
            float* p1 = g.C + (size_t)(r0 + 8) * g.N;
#pragma unroll
            for (int ni = 0; ni < 8; ni++) {
                const int col = n0 + warp_n * 64 + ni * 8 + 2 * tq;
                if (col < g.N) {
                    float b0 = __ldg(g.bias1 + col);
                    float e0 = fast_exp(acc[mi][ni][0] + b0);
                    float e2 = fast_exp(acc[mi][ni][2] + b0);
                    p0[col] = e0; p1[col] = e2;
                    rs0 += e0; rs1 += e2;
                }
                if (col + 1 < g.N) {
                    float b1 = __ldg(g.bias1 + col + 1);
                    float e1 = fast_exp(acc[mi][ni][1] + b1);
                    float e3 = fast_exp(acc[mi][ni][3] + b1);
                    p0[col + 1] = e1; p1[col + 1] = e3;
                    rs0 += e1; rs1 += e3;
                }
            }
            rs0 += __shfl_xor_sync(0xffffffffu, rs0, 1);
            rs0 += __shfl_xor_sync(0xffffffffu, rs0, 2);
            rs1 += __shfl_xor_sync(0xffffffffu, rs1, 1);
            rs1 += __shfl_xor_sync(0xffffffffu, rs1, 2);
            if (tq == 0) {
                red[warp_n * 128 + rl0]     = rs0;
                red[warp_n * 128 + rl0 + 8] = rs1;
            }
        }
        __syncthreads();
        if (tid < 128) {
            float s = red[tid] + red[128 + tid];
            g.partials[(size_t)(m0 + tid) * NBSTRIDE + blockIdx.y] = s;
        }
    }
}

// ---------------------------------------------------------------------------
// partials -> rowsum
// ---------------------------------------------------------------------------
__global__ void reduce_rowsum_kernel(const float* __restrict__ partials,
                                     float* __restrict__ rowsum, int nblocks) {
    int r = blockIdx.x * blockDim.x + threadIdx.x;
    if (r >= DB) return;
    const float* p = partials + (size_t)r * NBSTRIDE;
    float s = 0.f;
    for (int i = 0; i < nblocks; i++) s += p[i];
    rowsum[r] = s;
}

// scale: probs (holding exp values) *= 1/rowsum
__global__ __launch_bounds__(256) void softmax_scale_kernel(float* __restrict__ x,
                                                            const float* __restrict__ rowsum,
                                                            int N) {
    float* p = x + (size_t)blockIdx.x * N;
    const float inv = 1.f / rowsum[blockIdx.x];
    for (int i = threadIdx.x; i < N; i += 256) p[i] *= inv;
}

// ---------------------------------------------------------------------------
// fp32 -> fp16 conversion (n divisible by 8)
// ---------------------------------------------------------------------------
__global__ __launch_bounds__(256) void f2h_kernel(const float* __restrict__ x,
                                                  __half* __restrict__ y, int n) {
    int i = (blockIdx.x * blockDim.x + threadIdx.x) * 8;
    if (i >= n) return;
    float4 v0 = *reinterpret_cast<const float4*>(x + i);
    float4 v1 = *reinterpret_cast<const float4*>(x + i + 4);
    __half2 h[4];
    h[0] = __floats2half2_rn(v0.x, v0.y);
    h[1] = __floats2half2_rn(v0.z, v0.w);
    h[2] = __floats2half2_rn(v1.x, v1.y);
    h[3] = __floats2half2_rn(v1.z, v1.w);
    *reinterpret_cast<uint4*>(y + i) = *reinterpret_cast<uint4*>(h);
}

// ---------------------------------------------------------------------------
// LSTM cell elementwise; also emits hn in fp16 for the logits GEMM
// ---------------------------------------------------------------------------
__device__ __forceinline__ float sigmoidf_(float x) { return 1.f / (1.f + expf(-x)); }

__global__ void lstm_cell_kernel(const float* __restrict__ gates,
                                 const float* __restrict__ c0,
                                 float* __restrict__ hn,
                                 float* __restrict__ cn,
                                 __half* __restrict__ hn_h) {
    int idx = blockIdx.x * blockDim.x + threadIdx.x;
    if (idx >= DB * DH) return;
    int b = idx / DH;
    int h = idx % DH;
    const float* gr = gates + (size_t)b * 4 * DH;
    float ig = sigmoidf_(gr[h]);
    float fg = sigmoidf_(gr[DH + h]);
    float gg = tanhf(gr[2 * DH + h]);
    float og = sigmoidf_(gr[3 * DH + h]);
    float c = fg * c0[idx] + ig * gg;
    float hv = og * tanhf(c);
    cn[idx] = c;
    hn[idx] = hv;
    hn_h[idx] = __float2half_rn(hv);
}

// ---------------------------------------------------------------------------
extern "C" void kernel_launch(void* const* d_in, const int* in_sizes, int n_in,
                              void* d_out, int out_size)
{
    const float* input  = (const float*)d_in[0];
    const float* hidden = (const float*)d_in[1];
    const float* c0     = (const float*)d_in[2];
    const float* w_ih   = (const float*)d_in[3];
    const float* w_hh   = (const float*)d_in[4];
    const float* b_ih   = (const float*)d_in[5];
    const float* b_hh   = (const float*)d_in[6];
    const float* w_lin  = (const float*)d_in[7];
    const float* b_lin  = (const float*)d_in[8];

    float* out   = (float*)d_out;
    float* probs = out;                              // [B, O]
    float* hn    = out + (size_t)DB * DO;            // [B, H]
    float* cn    = hn + (size_t)DB * DH;             // [B, H]

    float *gates, *rowsum, *partials;
    __half *wih_h, *whh_h, *in_h, *hid_h, *wlin_h, *hn_h;
    cudaGetSymbolAddress((void**)&gates,    g_gates);
    cudaGetSymbolAddress((void**)&rowsum,   g_rowsum);
    cudaGetSymbolAddress((void**)&partials, g_partials);
    cudaGetSymbolAddress((void**)&wih_h,    g_wih_h);
    cudaGetSymbolAddress((void**)&whh_h,    g_whh_h);
    cudaGetSymbolAddress((void**)&in_h,     g_in_h);
    cudaGetSymbolAddress((void**)&hid_h,    g_hid_h);
    cudaGetSymbolAddress((void**)&wlin_h,   g_wlin_h);
    cudaGetSymbolAddress((void**)&hn_h,     g_hn_h);

    cudaFuncSetAttribute(f16_gemm_kernel<false>,
                         cudaFuncAttributeMaxDynamicSharedMemorySize, SMEM_BYTES);
    cudaFuncSetAttribute(f16_gemm_kernel<true>,
                         cudaFuncAttributeMaxDynamicSharedMemorySize, SMEM_BYTES);

    // fp16 conversions
    {
        int n;
        n = DB * DI;      f2h_kernel<<<(n / 8 + 255) / 256, 256>>>(input,  in_h,  n);
        n = DB * DH;      f2h_kernel<<<(n / 8 + 255) / 256, 256>>>(hidden, hid_h, n);
        n = 4 * DH * DI;  f2h_kernel<<<(n / 8 + 255) / 256, 256>>>(w_ih,   wih_h, n);
        n = 4 * DH * DH;  f2h_kernel<<<(n / 8 + 255) / 256, 256>>>(w_hh,   whh_h, n);
        n = DO * DH;      f2h_kernel<<<(n / 8 + 255) / 256, 256>>>(w_lin,  wlin_h, n);
    }

    // gates = input @ w_ih^T + h0 @ w_hh^T + b_ih + b_hh
    {
        GemmArgs a;
        a.pass[0] = { in_h,  wih_h, DI };
        a.pass[1] = { hid_h, whh_h, DH };
        a.npass = 2;
        a.bias1 = b_ih;
        a.bias2 = b_hh;
        a.C = gates;
        a.partials = nullptr;
        a.N = 4 * DH;
        dim3 grid(DB / 128, (4 * DH) / 128);
        f16_gemm_kernel<false><<<grid, 256, SMEM_BYTES>>>(a);
    }

    // LSTM cell -> hn, cn (+ hn fp16)
    lstm_cell_kernel<<<(DB * DH + 255) / 256, 256>>>(gates, c0, hn, cn, hn_h);

    // probs_unnorm = exp(hn @ w_lin^T + b_lin); partial row sums
    const int nblocks = (DO + 127) / 128;   // 393
    {
        GemmArgs a;
        a.pass[0] = { hn_h, wlin_h, DH };
        a.npass = 1;
        a.bias1 = b_lin;
        a.bias2 = nullptr;
        a.C = probs;
        a.partials = partials;
        a.N = DO;
        dim3 grid(DB / 128, nblocks);
        f16_gemm_kernel<true><<<grid, 256, SMEM_BYTES>>>(a);
    }

    // rowsum + scale
    reduce_rowsum_kernel<<<4, 256>>>(partials, rowsum, nblocks);
    softmax_scale_kernel<<<DB, 256>>>(probs, rowsum, DO);
}